// round 1
// baseline (speedup 1.0000x reference)
#include <cuda_runtime.h>

// Problem constants
#define BB 16
#define CC_ 256
#define HW 4096
#define NHEAD 4
#define DHEAD 64
#define NGROUP 8
#define CPG 32          // channels per group
#define EPSV 1e-5f

#define TOTAL (BB*CC_*HW)   // 16,777,216

// Scratch (device globals; no allocations allowed)
__device__ float g_xn[TOTAL];
__device__ float g_q [TOTAL];
__device__ float g_k [TOTAL];
__device__ float g_v [TOTAL];
__device__ float g_ao[TOTAL];
__device__ float g_mean[BB*NGROUP];
__device__ float g_rstd[BB*NGROUP];

// ---------------------------------------------------------------------------
// 1) GroupNorm statistics: one block per (b, group). 32 ch * 4096 = 131072 el.
// ---------------------------------------------------------------------------
__global__ __launch_bounds__(256) void gn_stats_kernel(const float* __restrict__ x)
{
    const int bg  = blockIdx.x;                 // b*8+g ; groups are contiguous in c
    const int tid = threadIdx.x;
    const float4* p4 = (const float4*)(x + (size_t)bg * CPG * HW);

    float s = 0.f, s2 = 0.f;
    for (int i = tid; i < CPG*HW/4; i += 256) {
        float4 v = p4[i];
        s  += v.x + v.y + v.z + v.w;
        s2 += v.x*v.x + v.y*v.y + v.z*v.z + v.w*v.w;
    }
    __shared__ float rs[256], rs2[256];
    rs[tid] = s; rs2[tid] = s2;
    __syncthreads();
    for (int off = 128; off > 0; off >>= 1) {
        if (tid < off) { rs[tid] += rs[tid+off]; rs2[tid] += rs2[tid+off]; }
        __syncthreads();
    }
    if (tid == 0) {
        const float inv_n = 1.f / (float)(CPG*HW);
        float mean = rs[0] * inv_n;
        float var  = rs2[0] * inv_n - mean*mean;
        g_mean[bg] = mean;
        g_rstd[bg] = rsqrtf(var + EPSV);
    }
}

// ---------------------------------------------------------------------------
// 2) GroupNorm apply (vectorized elementwise): xn = x*(rstd*w) + (b - mean*rstd*w)
// ---------------------------------------------------------------------------
__global__ __launch_bounds__(256) void gn_apply_kernel(const float* __restrict__ x,
                                                       const float* __restrict__ nw,
                                                       const float* __restrict__ nb)
{
    const int t = blockIdx.x * 256 + threadIdx.x;      // over TOTAL/4 float4s
    const int c  = (t >> 10) & 255;                    // (4t/4096) % 256
    const int bg = t >> 15;                            // 4t / 131072
    const float rstd = g_rstd[bg];
    const float mean = g_mean[bg];
    const float sw = nw[c] * rstd;
    const float sb = nb[c] - mean * sw;
    float4 v = ((const float4*)x)[t];
    v.x = v.x*sw + sb; v.y = v.y*sw + sb; v.z = v.z*sw + sb; v.w = v.w*sw + sb;
    ((float4*)g_xn)[t] = v;
}

// ---------------------------------------------------------------------------
// 3) QKV GEMM: per batch, out[o,n] = sum_c W[o,c]*xn[c,n] + bias[o]
//    o in [0,768): part=o>>8 -> q/k/v, channel co=o&255. Output layout [b][co][n].
//    64x64 tile, 256 thr, 4x4 micro. As[oo][cc] (bcast reads), Bs[cc][nn] (2-way).
// ---------------------------------------------------------------------------
__global__ __launch_bounds__(256) void qkv_gemm_kernel(const float* __restrict__ w,
                                                       const float* __restrict__ bias)
{
    const int b  = blockIdx.z;
    const int o0 = blockIdx.y * 64;
    const int n0 = blockIdx.x * 64;
    const int tid = threadIdx.x;
    const int tx = tid & 15, ty = tid >> 4;

    __shared__ float As[64][65];   // [oo][cc]
    __shared__ float Bs[64][65];   // [cc][nn]

    const float* xb = g_xn + (size_t)b * CC_ * HW;
    float acc[4][4] = {};

    const int lc = tid & 63;       // contiguous load dim
    const int lr = tid >> 6;       // 0..3

    for (int c0 = 0; c0 < CC_; c0 += 64) {
        #pragma unroll
        for (int k = 0; k < 16; k++) {
            const int r = lr + k*4;
            As[r][lc] = w[(size_t)(o0 + r) * CC_ + c0 + lc];
            Bs[r][lc] = xb[(size_t)(c0 + r) * HW + n0 + lc];
        }
        __syncthreads();
        #pragma unroll 8
        for (int kk = 0; kk < 64; kk++) {
            float a[4], bv[4];
            #pragma unroll
            for (int ii = 0; ii < 4; ii++) a[ii] = As[ty*4+ii][kk];
            #pragma unroll
            for (int jj = 0; jj < 4; jj++) bv[jj] = Bs[kk][tx*4+jj];
            #pragma unroll
            for (int ii = 0; ii < 4; ii++)
                #pragma unroll
                for (int jj = 0; jj < 4; jj++)
                    acc[ii][jj] += a[ii] * bv[jj];
        }
        __syncthreads();
    }

    #pragma unroll
    for (int ii = 0; ii < 4; ii++) {
        const int o = o0 + ty*4 + ii;
        const float bv = bias[o];
        const int part = o >> 8;
        const int co   = o & 255;
        float* dst = (part == 0) ? g_q : (part == 1) ? g_k : g_v;
        float4 r;
        r.x = acc[ii][0] + bv; r.y = acc[ii][1] + bv;
        r.z = acc[ii][2] + bv; r.w = acc[ii][3] + bv;
        *(float4*)&dst[(size_t)(b*CC_ + co) * HW + n0 + tx*4] = r;
    }
}

// ---------------------------------------------------------------------------
// 4) "Attention" mix: per (b, e) with e in [0,64):
//    G[i][j] = 0.125 * sum_s q[b, i*64+e, s] * k[b, j*64+e, s]   (i,j in [0,4))
//    P = softmax_j(G);  ao[b, i*64+e, s] = sum_j P[i][j]*v[b, j*64+e, s]
// ---------------------------------------------------------------------------
__global__ __launch_bounds__(256) void mix_kernel()
{
    const int be = blockIdx.x;           // 0..1023
    const int b  = be >> 6;
    const int e  = be & 63;
    const int tid = threadIdx.x;

    const size_t base = (size_t)(b*CC_ + e) * HW;   // channel i*64+e -> +i*64*HW
    const float* qp = g_q + base;
    const float* kp = g_k + base;
    const float* vp = g_v + base;

    float acc[16] = {};
    for (int s = tid; s < HW; s += 256) {
        float qv[4], kv[4];
        #pragma unroll
        for (int i = 0; i < 4; i++) qv[i] = qp[(size_t)i*DHEAD*HW + s];
        #pragma unroll
        for (int j = 0; j < 4; j++) kv[j] = kp[(size_t)j*DHEAD*HW + s];
        #pragma unroll
        for (int i = 0; i < 4; i++)
            #pragma unroll
            for (int j = 0; j < 4; j++)
                acc[i*4+j] += qv[i] * kv[j];
    }

    __shared__ float red[16][264];
    __shared__ float P[4][4];
    #pragma unroll
    for (int v = 0; v < 16; v++) red[v][tid] = acc[v];
    __syncthreads();

    if (tid < 16) {
        float s = 0.f;
        for (int t = 0; t < 256; t++) s += red[tid][t];
        red[tid][256] = s * 0.125f;     // scale = dh^-0.5
    }
    __syncthreads();
    if (tid < 4) {
        float g0 = red[tid*4+0][256], g1 = red[tid*4+1][256];
        float g2 = red[tid*4+2][256], g3 = red[tid*4+3][256];
        float m = fmaxf(fmaxf(g0, g1), fmaxf(g2, g3));
        float e0 = expf(g0-m), e1 = expf(g1-m), e2 = expf(g2-m), e3 = expf(g3-m);
        float inv = 1.f / (e0+e1+e2+e3);
        P[tid][0] = e0*inv; P[tid][1] = e1*inv; P[tid][2] = e2*inv; P[tid][3] = e3*inv;
    }
    __syncthreads();

    float p[4][4];
    #pragma unroll
    for (int i = 0; i < 4; i++)
        #pragma unroll
        for (int j = 0; j < 4; j++) p[i][j] = P[i][j];

    for (int s = tid; s < HW; s += 256) {
        float vv[4];
        #pragma unroll
        for (int j = 0; j < 4; j++) vv[j] = vp[(size_t)j*DHEAD*HW + s];
        #pragma unroll
        for (int i = 0; i < 4; i++) {
            float o = p[i][0]*vv[0] + p[i][1]*vv[1] + p[i][2]*vv[2] + p[i][3]*vv[3];
            g_ao[base + (size_t)i*DHEAD*HW + s] = o;
        }
    }
}

// ---------------------------------------------------------------------------
// 5) Proj GEMM + bias + residual: out[b,o,n] = sum_c Pw[o,c]*ao[b,c,n] + pb[o] + x[b,o,n]
// ---------------------------------------------------------------------------
__global__ __launch_bounds__(256) void proj_gemm_kernel(const float* __restrict__ w,
                                                        const float* __restrict__ bias,
                                                        const float* __restrict__ x,
                                                        float* __restrict__ out)
{
    const int b  = blockIdx.z;
    const int o0 = blockIdx.y * 64;
    const int n0 = blockIdx.x * 64;
    const int tid = threadIdx.x;
    const int tx = tid & 15, ty = tid >> 4;

    __shared__ float As[64][65];   // [oo][cc]
    __shared__ float Bs[64][65];   // [cc][nn]

    const float* ab = g_ao + (size_t)b * CC_ * HW;
    float acc[4][4] = {};

    const int lc = tid & 63;
    const int lr = tid >> 6;

    for (int c0 = 0; c0 < CC_; c0 += 64) {
        #pragma unroll
        for (int k = 0; k < 16; k++) {
            const int r = lr + k*4;
            As[r][lc] = w[(size_t)(o0 + r) * CC_ + c0 + lc];
            Bs[r][lc] = ab[(size_t)(c0 + r) * HW + n0 + lc];
        }
        __syncthreads();
        #pragma unroll 8
        for (int kk = 0; kk < 64; kk++) {
            float a[4], bv[4];
            #pragma unroll
            for (int ii = 0; ii < 4; ii++) a[ii] = As[ty*4+ii][kk];
            #pragma unroll
            for (int jj = 0; jj < 4; jj++) bv[jj] = Bs[kk][tx*4+jj];
            #pragma unroll
            for (int ii = 0; ii < 4; ii++)
                #pragma unroll
                for (int jj = 0; jj < 4; jj++)
                    acc[ii][jj] += a[ii] * bv[jj];
        }
        __syncthreads();
    }

    #pragma unroll
    for (int ii = 0; ii < 4; ii++) {
        const int o = o0 + ty*4 + ii;
        const float bv = bias[o];
        const size_t idx = (size_t)(b*CC_ + o) * HW + n0 + tx*4;
        float4 xr = *(const float4*)&x[idx];
        float4 r;
        r.x = acc[ii][0] + bv + xr.x;
        r.y = acc[ii][1] + bv + xr.y;
        r.z = acc[ii][2] + bv + xr.z;
        r.w = acc[ii][3] + bv + xr.w;
        *(float4*)&out[idx] = r;
    }
}

// ---------------------------------------------------------------------------
extern "C" void kernel_launch(void* const* d_in, const int* in_sizes, int n_in,
                              void* d_out, int out_size)
{
    const float* x      = (const float*)d_in[0];
    const float* norm_w = (const float*)d_in[1];
    const float* norm_b = (const float*)d_in[2];
    const float* qkv_w  = (const float*)d_in[3];
    const float* qkv_b  = (const float*)d_in[4];
    const float* proj_w = (const float*)d_in[5];
    const float* proj_b = (const float*)d_in[6];
    float* out = (float*)d_out;

    gn_stats_kernel<<<BB*NGROUP, 256>>>(x);
    gn_apply_kernel<<<TOTAL/4/256, 256>>>(x, norm_w, norm_b);
    qkv_gemm_kernel<<<dim3(HW/64, 768/64, BB), 256>>>(qkv_w, qkv_b);
    mix_kernel<<<BB*DHEAD, 256>>>();
    proj_gemm_kernel<<<dim3(HW/64, CC_/64, BB), 256>>>(proj_w, proj_b, x, out);
}

// round 7
// speedup vs baseline: 3.9016x; 3.9016x over previous
#include <cuda_runtime.h>
#include <cuda_bf16.h>
#include <cstdint>

// ---------------------------------------------------------------- constants
#define BB 16
#define CC_ 256
#define HWN 4096
#define EPSV 1e-5f
#define TOTAL (BB*CC_*HWN)   // 16,777,216

// ---------------------------------------------------------------- scratch
__device__ float g_q [TOTAL];
__device__ float g_k [TOTAL];
__device__ float g_v [TOTAL];
__device__ float g_ao[TOTAL];
__device__ __nv_bfloat16 g_xnT_hi[TOTAL];
__device__ __nv_bfloat16 g_xnT_lo[TOTAL];
__device__ __nv_bfloat16 g_aoT_hi[TOTAL];
__device__ __nv_bfloat16 g_aoT_lo[TOTAL];
__device__ __nv_bfloat16 g_wqkv_hi[768*256];
__device__ __nv_bfloat16 g_wqkv_lo[768*256];
__device__ __nv_bfloat16 g_wproj_hi[256*256];
__device__ __nv_bfloat16 g_wproj_lo[256*256];
__device__ float g_mean[BB*8];
__device__ float g_rstd[BB*8];

// ---------------------------------------------------------------- PTX helpers
__device__ __forceinline__ uint32_t smem_u32(const void* p) {
    uint32_t a;
    asm("{ .reg .u64 t; cvta.to.shared.u64 t, %1; cvt.u32.u64 %0, t; }" : "=r"(a) : "l"(p));
    return a;
}
__device__ __forceinline__ void ldsm4(uint32_t* r, uint32_t addr) {
    asm volatile("ldmatrix.sync.aligned.m8n8.x4.shared.b16 {%0,%1,%2,%3}, [%4];"
                 : "=r"(r[0]), "=r"(r[1]), "=r"(r[2]), "=r"(r[3]) : "r"(addr));
}
__device__ __forceinline__ void mma16816(float* d, const uint32_t* a, const uint32_t* b) {
    asm volatile("mma.sync.aligned.m16n8k16.row.col.f32.bf16.bf16.f32 "
                 "{%0,%1,%2,%3}, {%4,%5,%6,%7}, {%8,%9}, {%0,%1,%2,%3};"
                 : "+f"(d[0]), "+f"(d[1]), "+f"(d[2]), "+f"(d[3])
                 : "r"(a[0]), "r"(a[1]), "r"(a[2]), "r"(a[3]), "r"(b[0]), "r"(b[1]));
}
__device__ __forceinline__ void cpasync16(uint32_t dst, const void* src) {
    asm volatile("cp.async.cg.shared.global [%0], [%1], 16;" :: "r"(dst), "l"(src));
}
#define CP_COMMIT() asm volatile("cp.async.commit_group;" ::: "memory")
#define CP_WAIT_1() asm volatile("cp.async.wait_group 1;" ::: "memory")
#define CP_WAIT_0() asm volatile("cp.async.wait_group 0;" ::: "memory")

// 16B-unit swizzled offset inside an 8KB region: 128 rows x 4 units (64B row)
__device__ __forceinline__ uint32_t swz_unit(int row, int u) {
    return (uint32_t)((row*4 + (u ^ ((row >> 1) & 3))) * 16);
}

// ---------------------------------------------------------------- 1) GN stats
__global__ __launch_bounds__(256) void gn_stats_kernel(const float* __restrict__ x)
{
    const int bg  = blockIdx.x;
    const int tid = threadIdx.x;
    const float4* p4 = (const float4*)(x + (size_t)bg * 32 * HWN);
    float s = 0.f, s2 = 0.f;
    for (int i = tid; i < 32*HWN/4; i += 256) {
        float4 v = p4[i];
        s  += v.x + v.y + v.z + v.w;
        s2 += v.x*v.x + v.y*v.y + v.z*v.z + v.w*v.w;
    }
    __shared__ float rs[256], rs2[256];
    rs[tid] = s; rs2[tid] = s2;
    __syncthreads();
    for (int off = 128; off > 0; off >>= 1) {
        if (tid < off) { rs[tid] += rs[tid+off]; rs2[tid] += rs2[tid+off]; }
        __syncthreads();
    }
    if (tid == 0) {
        const float inv_n = 1.f / (float)(32*HWN);
        float mean = rs[0] * inv_n;
        float var  = rs2[0] * inv_n - mean*mean;
        g_mean[bg] = mean;
        g_rstd[bg] = rsqrtf(var + EPSV);
    }
}

// ------------------------------------------- 2) GN apply + transpose -> bf16 hi/lo [b][n][c]
__global__ __launch_bounds__(256) void gn_apply_t_kernel(const float* __restrict__ x,
                                                         const float* __restrict__ nw,
                                                         const float* __restrict__ nb)
{
    const int nt = blockIdx.x, ct = blockIdx.y, b = blockIdx.z;
    const int n0 = nt*32, c0 = ct*32;
    __shared__ float tile[32][33];
    const int col = threadIdx.x & 31, r = threadIdx.x >> 5;
    #pragma unroll
    for (int p = 0; p < 4; p++) {
        int cl = r + p*8;
        int c = c0 + cl;
        float rstd = g_rstd[b*8 + (c >> 5)];
        float mean = g_mean[b*8 + (c >> 5)];
        float sw = nw[c]*rstd, sb2 = nb[c] - mean*sw;
        float v = x[((size_t)(b*CC_+c))*HWN + n0 + col];
        tile[cl][col] = v*sw + sb2;
    }
    __syncthreads();
    #pragma unroll
    for (int p = 0; p < 4; p++) {
        int nl = r + p*8;
        float v = tile[col][nl];
        __nv_bfloat16 hi = __float2bfloat16(v);
        __nv_bfloat16 lo = __float2bfloat16(v - __bfloat162float(hi));
        size_t idx = ((size_t)(b*HWN + n0 + nl))*CC_ + c0 + col;
        g_xnT_hi[idx] = hi; g_xnT_lo[idx] = lo;
    }
}

// ---------------------------------------------------------------- 3) weight prep
__global__ __launch_bounds__(256) void wprep_kernel(const float* __restrict__ qkv_w,
                                                    const float* __restrict__ proj_w)
{
    const int i = blockIdx.x * 256 + threadIdx.x;
    if (i < 768*256) {
        float v = qkv_w[i];
        __nv_bfloat16 hi = __float2bfloat16(v);
        g_wqkv_hi[i] = hi;
        g_wqkv_lo[i] = __float2bfloat16(v - __bfloat162float(hi));
    }
    if (i < 256*256) {
        float v = proj_w[i];
        __nv_bfloat16 hi = __float2bfloat16(v);
        g_wproj_hi[i] = hi;
        g_wproj_lo[i] = __float2bfloat16(v - __bfloat162float(hi));
    }
}

// ---------------------------------------------------------------- HMMA GEMM
// D[m0+row, n0+col] = sum_c W[m0+row, c] * X[b, n0+col, c]   (K=256, 8 chunks of 32)
// CTA tile 128x128, 8 warps (2 along M x 4 along N), warp tile 64x32.
// 3 passes: Ahi*Bhi + Ahi*Blo + Alo*Bhi.
// MODE 0: qkv -> q/k/v fp32 [b][c][n] (+bias). MODE 1: proj -> out = D + bias + x.
// SMEM: per buffer 32KB = Ahi(8K) Alo(8K) Bhi(8K) Blo(8K); double buffered = 64KB.
#define SMEM_TOTAL_MMA 65536

template<int MODE>
__global__ __launch_bounds__(256, 1) void hmma_gemm_kernel(const float* __restrict__ bias,
                                                           const float* __restrict__ xres,
                                                           float* __restrict__ out)
{
    extern __shared__ char smem[];
    const uint32_t sb = smem_u32(smem);
    const int tid = threadIdx.x;
    const int lane = tid & 31, wid = tid >> 5;
    const int wm = wid & 1, wn = wid >> 1;
    const int n0 = blockIdx.x * 128, m0 = blockIdx.y * 128, b = blockIdx.z;

    const __nv_bfloat16* __restrict__ Whi = (MODE == 0) ? g_wqkv_hi : g_wproj_hi;
    const __nv_bfloat16* __restrict__ Wlo = (MODE == 0) ? g_wqkv_lo : g_wproj_lo;
    const __nv_bfloat16* __restrict__ Xhi = (MODE == 0) ? g_xnT_hi  : g_aoT_hi;
    const __nv_bfloat16* __restrict__ Xlo = (MODE == 0) ? g_xnT_lo  : g_aoT_lo;

    float acc[4][4][4] = {};

    // per-thread load coords (2 iterations of 256 threads cover 512 16B units)
    const int row_a = tid >> 2, u_a = tid & 3;

    auto load_chunk = [&](int chunk, int buf) {
        const int c0 = chunk * 32;
        const uint32_t base = sb + (uint32_t)buf * 32768u;
        #pragma unroll
        for (int it = 0; it < 2; it++) {
            const int row = row_a + it*64;
            const uint32_t du = swz_unit(row, u_a);
            const size_t sa = (size_t)(m0 + row)*256 + c0 + u_a*8;
            cpasync16(base +         du, Whi + sa);
            cpasync16(base + 8192u + du, Wlo + sa);
            const size_t sx = (size_t)(b*HWN + n0 + row)*256 + c0 + u_a*8;
            cpasync16(base + 16384u + du, Xhi + sx);
            cpasync16(base + 24576u + du, Xlo + sx);
        }
    };

    auto compute = [&](int buf) {
        const uint32_t base = sb + (uint32_t)buf * 32768u;
        #pragma unroll
        for (int ks = 0; ks < 2; ks++) {
            uint32_t ahi[4][4], alo[4][4], bhi[4][2], blo[4][2];
            #pragma unroll
            for (int i = 0; i < 4; i++) {
                const int row = wm*64 + i*16 + (lane & 15);
                const int u   = ks*2 + (lane >> 4);
                const uint32_t ad = swz_unit(row, u);
                ldsm4(ahi[i], base +         ad);
                ldsm4(alo[i], base + 8192u + ad);
            }
            #pragma unroll
            for (int jj = 0; jj < 2; jj++) {
                const int row = wn*32 + jj*16 + ((lane >> 4) & 1)*8 + (lane & 7);
                const int u   = ks*2 + ((lane >> 3) & 1);
                const uint32_t bd = swz_unit(row, u);
                uint32_t r[4];
                ldsm4(r, base + 16384u + bd);
                bhi[jj*2+0][0] = r[0]; bhi[jj*2+0][1] = r[1];
                bhi[jj*2+1][0] = r[2]; bhi[jj*2+1][1] = r[3];
                ldsm4(r, base + 24576u + bd);
                blo[jj*2+0][0] = r[0]; blo[jj*2+0][1] = r[1];
                blo[jj*2+1][0] = r[2]; blo[jj*2+1][1] = r[3];
            }
            #pragma unroll
            for (int i = 0; i < 4; i++)
                #pragma unroll
                for (int j = 0; j < 4; j++)
                    mma16816(acc[i][j], ahi[i], bhi[j]);
            #pragma unroll
            for (int i = 0; i < 4; i++)
                #pragma unroll
                for (int j = 0; j < 4; j++)
                    mma16816(acc[i][j], ahi[i], blo[j]);
            #pragma unroll
            for (int i = 0; i < 4; i++)
                #pragma unroll
                for (int j = 0; j < 4; j++)
                    mma16816(acc[i][j], alo[i], bhi[j]);
        }
    };

    load_chunk(0, 0); CP_COMMIT();
    for (int c = 0; c < 8; c++) {
        if (c < 7) {
            load_chunk(c + 1, (c + 1) & 1); CP_COMMIT();
            CP_WAIT_1();
        } else {
            CP_WAIT_0();
        }
        __syncthreads();
        compute(c & 1);
        __syncthreads();
    }

    // ---------------- epilogue ----------------
    #pragma unroll
    for (int i = 0; i < 4; i++) {
        const int row0 = m0 + wm*64 + i*16 + (lane >> 2);
        #pragma unroll
        for (int half = 0; half < 2; half++) {
            const int o = row0 + half*8;
            const float bv = bias[o];
            float* dst;
            const float* xr = nullptr;
            if (MODE == 0) {
                const int part = o >> 8, co = o & 255;
                float* basep = (part == 0) ? g_q : (part == 1) ? g_k : g_v;
                dst = basep + ((size_t)(b*CC_ + co))*HWN + n0;
            } else {
                const size_t off = ((size_t)(b*CC_ + o))*HWN + n0;
                dst = out + off;
                xr  = xres + off;
            }
            #pragma unroll
            for (int j = 0; j < 4; j++) {
                const int col = wn*32 + j*8 + (lane & 3)*2;
                float2 t;
                t.x = acc[i][j][half*2+0] + bv;
                t.y = acc[i][j][half*2+1] + bv;
                if (MODE == 1) { t.x += xr[col]; t.y += xr[col+1]; }
                *(float2*)(dst + col) = t;
            }
        }
    }
}

// ---------------------------------------------------------------- 4) mix
__global__ __launch_bounds__(256) void mix_kernel()
{
    const int be = blockIdx.x;
    const int b  = be >> 6;
    const int e  = be & 63;
    const int tid = threadIdx.x;

    const size_t base = (size_t)(b*CC_ + e) * HWN;
    const float* qp = g_q + base;
    const float* kp = g_k + base;
    const float* vp = g_v + base;

    float acc[16] = {};
    for (int s = tid; s < HWN; s += 256) {
        float qv[4], kv[4];
        #pragma unroll
        for (int i = 0; i < 4; i++) qv[i] = qp[(size_t)i*64*HWN + s];
        #pragma unroll
        for (int j = 0; j < 4; j++) kv[j] = kp[(size_t)j*64*HWN + s];
        #pragma unroll
        for (int i = 0; i < 4; i++)
            #pragma unroll
            for (int j = 0; j < 4; j++)
                acc[i*4+j] += qv[i] * kv[j];
    }

    __shared__ float red[16][264];
    __shared__ float P[4][4];
    #pragma unroll
    for (int v = 0; v < 16; v++) red[v][tid] = acc[v];
    __syncthreads();

    if (tid < 16) {
        float s = 0.f;
        for (int t = 0; t < 256; t++) s += red[tid][t];
        red[tid][256] = s * 0.125f;
    }
    __syncthreads();
    if (tid < 4) {
        float g0 = red[tid*4+0][256], g1 = red[tid*4+1][256];
        float g2 = red[tid*4+2][256], g3 = red[tid*4+3][256];
        float m = fmaxf(fmaxf(g0, g1), fmaxf(g2, g3));
        float e0 = expf(g0-m), e1 = expf(g1-m), e2 = expf(g2-m), e3 = expf(g3-m);
        float inv = 1.f / (e0+e1+e2+e3);
        P[tid][0] = e0*inv; P[tid][1] = e1*inv; P[tid][2] = e2*inv; P[tid][3] = e3*inv;
    }
    __syncthreads();

    float p[4][4];
    #pragma unroll
    for (int i = 0; i < 4; i++)
        #pragma unroll
        for (int j = 0; j < 4; j++) p[i][j] = P[i][j];

    for (int s = tid; s < HWN; s += 256) {
        float vv[4];
        #pragma unroll
        for (int j = 0; j < 4; j++) vv[j] = vp[(size_t)j*64*HWN + s];
        #pragma unroll
        for (int i = 0; i < 4; i++) {
            float o = p[i][0]*vv[0] + p[i][1]*vv[1] + p[i][2]*vv[2] + p[i][3]*vv[3];
            g_ao[base + (size_t)i*64*HWN + s] = o;
        }
    }
}

// ------------------------------------------- 5) transpose ao -> bf16 hi/lo [b][n][c]
__global__ __launch_bounds__(256) void trans_ao_kernel()
{
    const int nt = blockIdx.x, ct = blockIdx.y, b = blockIdx.z;
    const int n0 = nt*32, c0 = ct*32;
    __shared__ float tile[32][33];
    const int col = threadIdx.x & 31, r = threadIdx.x >> 5;
    #pragma unroll
    for (int p = 0; p < 4; p++) {
        int cl = r + p*8;
        tile[cl][col] = g_ao[((size_t)(b*CC_ + c0 + cl))*HWN + n0 + col];
    }
    __syncthreads();
    #pragma unroll
    for (int p = 0; p < 4; p++) {
        int nl = r + p*8;
        float v = tile[col][nl];
        __nv_bfloat16 hi = __float2bfloat16(v);
        __nv_bfloat16 lo = __float2bfloat16(v - __bfloat162float(hi));
        size_t idx = ((size_t)(b*HWN + n0 + nl))*CC_ + c0 + col;
        g_aoT_hi[idx] = hi; g_aoT_lo[idx] = lo;
    }
}

// ---------------------------------------------------------------- launch
extern "C" void kernel_launch(void* const* d_in, const int* in_sizes, int n_in,
                              void* d_out, int out_size)
{
    const float* x      = (const float*)d_in[0];
    const float* norm_w = (const float*)d_in[1];
    const float* norm_b = (const float*)d_in[2];
    const float* qkv_w  = (const float*)d_in[3];
    const float* qkv_b  = (const float*)d_in[4];
    const float* proj_w = (const float*)d_in[5];
    const float* proj_b = (const float*)d_in[6];
    float* out = (float*)d_out;

    static bool attr_set = false;
    if (!attr_set) {
        cudaFuncSetAttribute(hmma_gemm_kernel<0>,
                             cudaFuncAttributeMaxDynamicSharedMemorySize, SMEM_TOTAL_MMA);
        cudaFuncSetAttribute(hmma_gemm_kernel<1>,
                             cudaFuncAttributeMaxDynamicSharedMemorySize, SMEM_TOTAL_MMA);
        attr_set = true;
    }

    gn_stats_kernel<<<BB*8, 256>>>(x);
    wprep_kernel<<<768, 256>>>(qkv_w, proj_w);
    gn_apply_t_kernel<<<dim3(128, 8, BB), 256>>>(x, norm_w, norm_b);
    hmma_gemm_kernel<0><<<dim3(32, 6, BB), 256, SMEM_TOTAL_MMA>>>(qkv_b, nullptr, nullptr);
    mix_kernel<<<BB*64, 256>>>();
    trans_ao_kernel<<<dim3(128, 8, BB), 256>>>();
    hmma_gemm_kernel<1><<<dim3(32, 2, BB), 256, SMEM_TOTAL_MMA>>>(proj_b, x, out);
}

// round 8
// speedup vs baseline: 4.3185x; 1.1069x over previous
#include <cuda_runtime.h>
#include <cuda_bf16.h>
#include <cstdint>

// ---------------------------------------------------------------- constants
#define BB 16
#define CC_ 256
#define HWN 4096
#define EPSV 1e-5f
#define TOTAL (BB*CC_*HWN)   // 16,777,216

// ---------------------------------------------------------------- scratch
__device__ float g_q [TOTAL];
__device__ float g_k [TOTAL];
__device__ float g_v [TOTAL];
__device__ float g_ao[TOTAL];
__device__ __nv_bfloat16 g_xnT_hi[TOTAL];
__device__ __nv_bfloat16 g_xnT_lo[TOTAL];
__device__ __nv_bfloat16 g_aoT_hi[TOTAL];
__device__ __nv_bfloat16 g_aoT_lo[TOTAL];
__device__ __nv_bfloat16 g_wqkv_hi[768*256];
__device__ __nv_bfloat16 g_wqkv_lo[768*256];
__device__ __nv_bfloat16 g_wproj_hi[256*256];
__device__ __nv_bfloat16 g_wproj_lo[256*256];
__device__ float g_mean[BB*8];
__device__ float g_rstd[BB*8];

// ---------------------------------------------------------------- PTX helpers
__device__ __forceinline__ uint32_t smem_u32(const void* p) {
    uint32_t a;
    asm("{ .reg .u64 t; cvta.to.shared.u64 t, %1; cvt.u32.u64 %0, t; }" : "=r"(a) : "l"(p));
    return a;
}
__device__ __forceinline__ void ldsm4(uint32_t* r, uint32_t addr) {
    asm volatile("ldmatrix.sync.aligned.m8n8.x4.shared.b16 {%0,%1,%2,%3}, [%4];"
                 : "=r"(r[0]), "=r"(r[1]), "=r"(r[2]), "=r"(r[3]) : "r"(addr));
}
__device__ __forceinline__ void mma16816(float* d, const uint32_t* a, const uint32_t* b) {
    asm volatile("mma.sync.aligned.m16n8k16.row.col.f32.bf16.bf16.f32 "
                 "{%0,%1,%2,%3}, {%4,%5,%6,%7}, {%8,%9}, {%0,%1,%2,%3};"
                 : "+f"(d[0]), "+f"(d[1]), "+f"(d[2]), "+f"(d[3])
                 : "r"(a[0]), "r"(a[1]), "r"(a[2]), "r"(a[3]), "r"(b[0]), "r"(b[1]));
}
__device__ __forceinline__ void cpasync16(uint32_t dst, const void* src) {
    asm volatile("cp.async.cg.shared.global [%0], [%1], 16;" :: "r"(dst), "l"(src));
}
#define CP_COMMIT() asm volatile("cp.async.commit_group;" ::: "memory")
#define CP_WAIT(n)  asm volatile("cp.async.wait_group %0;" :: "n"(n) : "memory")

// 16B-unit swizzled offset inside an 8KB region: 128 rows x 4 units (64B row)
__device__ __forceinline__ uint32_t swz_unit(int row, int u) {
    return (uint32_t)((row*4 + (u ^ ((row >> 1) & 3))) * 16);
}

// ---------------------------------------------------------------- 1) GN stats
__global__ __launch_bounds__(256) void gn_stats_kernel(const float* __restrict__ x)
{
    const int bg  = blockIdx.x;
    const int tid = threadIdx.x;
    const float4* p4 = (const float4*)(x + (size_t)bg * 32 * HWN);
    float s = 0.f, s2 = 0.f;
    for (int i = tid; i < 32*HWN/4; i += 256) {
        float4 v = p4[i];
        s  += v.x + v.y + v.z + v.w;
        s2 += v.x*v.x + v.y*v.y + v.z*v.z + v.w*v.w;
    }
    __shared__ float rs[256], rs2[256];
    rs[tid] = s; rs2[tid] = s2;
    __syncthreads();
    for (int off = 128; off > 0; off >>= 1) {
        if (tid < off) { rs[tid] += rs[tid+off]; rs2[tid] += rs2[tid+off]; }
        __syncthreads();
    }
    if (tid == 0) {
        const float inv_n = 1.f / (float)(32*HWN);
        float mean = rs[0] * inv_n;
        float var  = rs2[0] * inv_n - mean*mean;
        g_mean[bg] = mean;
        g_rstd[bg] = rsqrtf(var + EPSV);
    }
}

// ------------------------------------------- 2) GN apply + transpose -> bf16 hi/lo [b][n][c]
__global__ __launch_bounds__(256) void gn_apply_t_kernel(const float* __restrict__ x,
                                                         const float* __restrict__ nw,
                                                         const float* __restrict__ nb)
{
    const int nt = blockIdx.x, ct = blockIdx.y, b = blockIdx.z;
    const int n0 = nt*32, c0 = ct*32;
    __shared__ float tile[32][33];
    const int col = threadIdx.x & 31, r = threadIdx.x >> 5;
    #pragma unroll
    for (int p = 0; p < 4; p++) {
        int cl = r + p*8;
        int c = c0 + cl;
        float rstd = g_rstd[b*8 + (c >> 5)];
        float mean = g_mean[b*8 + (c >> 5)];
        float sw = nw[c]*rstd, sb2 = nb[c] - mean*sw;
        float v = x[((size_t)(b*CC_+c))*HWN + n0 + col];
        tile[cl][col] = v*sw + sb2;
    }
    __syncthreads();
    #pragma unroll
    for (int p = 0; p < 4; p++) {
        int nl = r + p*8;
        float v = tile[col][nl];
        __nv_bfloat16 hi = __float2bfloat16(v);
        __nv_bfloat16 lo = __float2bfloat16(v - __bfloat162float(hi));
        size_t idx = ((size_t)(b*HWN + n0 + nl))*CC_ + c0 + col;
        g_xnT_hi[idx] = hi; g_xnT_lo[idx] = lo;
    }
}

// ---------------------------------------------------------------- 3) weight prep
__global__ __launch_bounds__(256) void wprep_kernel(const float* __restrict__ qkv_w,
                                                    const float* __restrict__ proj_w)
{
    const int i = blockIdx.x * 256 + threadIdx.x;
    if (i < 768*256) {
        float v = qkv_w[i];
        __nv_bfloat16 hi = __float2bfloat16(v);
        g_wqkv_hi[i] = hi;
        g_wqkv_lo[i] = __float2bfloat16(v - __bfloat162float(hi));
    }
    if (i < 256*256) {
        float v = proj_w[i];
        __nv_bfloat16 hi = __float2bfloat16(v);
        g_wproj_hi[i] = hi;
        g_wproj_lo[i] = __float2bfloat16(v - __bfloat162float(hi));
    }
}

// ---------------------------------------------------------------- HMMA GEMM
// D[m0+row, n0+col] = sum_c W[m0+row, c] * X[b, n0+col, c]   (K=256, 8 chunks of 32)
// CTA tile 128x128, 8 warps (2 along M x 4 along N), warp tile 64x32.
// 3 passes: Ahi*Bhi + Ahi*Blo + Alo*Bhi.
// 4-stage cp.async pipeline, one __syncthreads per chunk.
// MODE 0: qkv -> q/k/v fp32 [b][c][n] (+bias). MODE 1: proj -> out = D + bias + x.
#define STAGE_BYTES 32768
#define NSTAGE 4
#define SMEM_TOTAL_MMA (STAGE_BYTES*NSTAGE)   // 131072

template<int MODE>
__global__ __launch_bounds__(256, 1) void hmma_gemm_kernel(const float* __restrict__ bias,
                                                           const float* __restrict__ xres,
                                                           float* __restrict__ out)
{
    extern __shared__ char smem[];
    const uint32_t sb = smem_u32(smem);
    const int tid = threadIdx.x;
    const int lane = tid & 31, wid = tid >> 5;
    const int wm = wid & 1, wn = wid >> 1;
    const int n0 = blockIdx.x * 128, m0 = blockIdx.y * 128, b = blockIdx.z;

    const __nv_bfloat16* __restrict__ Whi = (MODE == 0) ? g_wqkv_hi : g_wproj_hi;
    const __nv_bfloat16* __restrict__ Wlo = (MODE == 0) ? g_wqkv_lo : g_wproj_lo;
    const __nv_bfloat16* __restrict__ Xhi = (MODE == 0) ? g_xnT_hi  : g_aoT_hi;
    const __nv_bfloat16* __restrict__ Xlo = (MODE == 0) ? g_xnT_lo  : g_aoT_lo;

    float acc[4][4][4] = {};

    const int row_a = tid >> 2, u_a = tid & 3;

    auto load_chunk = [&](int chunk, int stage) {
        const int c0 = chunk * 32;
        const uint32_t base = sb + (uint32_t)stage * STAGE_BYTES;
        #pragma unroll
        for (int it = 0; it < 2; it++) {
            const int row = row_a + it*64;
            const uint32_t du = swz_unit(row, u_a);
            const size_t sa = (size_t)(m0 + row)*256 + c0 + u_a*8;
            cpasync16(base +         du, Whi + sa);
            cpasync16(base + 8192u + du, Wlo + sa);
            const size_t sx = (size_t)(b*HWN + n0 + row)*256 + c0 + u_a*8;
            cpasync16(base + 16384u + du, Xhi + sx);
            cpasync16(base + 24576u + du, Xlo + sx);
        }
        CP_COMMIT();
    };

    auto compute = [&](int stage) {
        const uint32_t base = sb + (uint32_t)stage * STAGE_BYTES;
        #pragma unroll
        for (int ks = 0; ks < 2; ks++) {
            uint32_t ahi[4][4], alo[4][4], bhi[4][2], blo[4][2];
            #pragma unroll
            for (int i = 0; i < 4; i++) {
                const int row = wm*64 + i*16 + (lane & 15);
                const int u   = ks*2 + (lane >> 4);
                const uint32_t ad = swz_unit(row, u);
                ldsm4(ahi[i], base +         ad);
                ldsm4(alo[i], base + 8192u + ad);
            }
            #pragma unroll
            for (int jj = 0; jj < 2; jj++) {
                const int row = wn*32 + jj*16 + ((lane >> 4) & 1)*8 + (lane & 7);
                const int u   = ks*2 + ((lane >> 3) & 1);
                const uint32_t bd = swz_unit(row, u);
                uint32_t r[4];
                ldsm4(r, base + 16384u + bd);
                bhi[jj*2+0][0] = r[0]; bhi[jj*2+0][1] = r[1];
                bhi[jj*2+1][0] = r[2]; bhi[jj*2+1][1] = r[3];
                ldsm4(r, base + 24576u + bd);
                blo[jj*2+0][0] = r[0]; blo[jj*2+0][1] = r[1];
                blo[jj*2+1][0] = r[2]; blo[jj*2+1][1] = r[3];
            }
            #pragma unroll
            for (int i = 0; i < 4; i++)
                #pragma unroll
                for (int j = 0; j < 4; j++)
                    mma16816(acc[i][j], ahi[i], bhi[j]);
            #pragma unroll
            for (int i = 0; i < 4; i++)
                #pragma unroll
                for (int j = 0; j < 4; j++)
                    mma16816(acc[i][j], ahi[i], blo[j]);
            #pragma unroll
            for (int i = 0; i < 4; i++)
                #pragma unroll
                for (int j = 0; j < 4; j++)
                    mma16816(acc[i][j], alo[i], bhi[j]);
        }
    };

    // prefetch NSTAGE-1 chunks
    load_chunk(0, 0);
    load_chunk(1, 1);
    load_chunk(2, 2);

    #pragma unroll
    for (int c = 0; c < 8; c++) {
        // wait until chunk c's group is complete: outstanding after = min(7-c, NSTAGE-2)
        if (c <= 5) CP_WAIT(2);
        else if (c == 6) CP_WAIT(1);
        else CP_WAIT(0);
        __syncthreads();
        // stage (c+3)%4 was consumed at iter c-1 -> safe to refill after this barrier
        if (c + 3 < 8) load_chunk(c + 3, (c + 3) & 3);
        compute(c & 3);
    }

    // ---------------- epilogue ----------------
    #pragma unroll
    for (int i = 0; i < 4; i++) {
        const int row0 = m0 + wm*64 + i*16 + (lane >> 2);
        #pragma unroll
        for (int half = 0; half < 2; half++) {
            const int o = row0 + half*8;
            const float bv = bias[o];
            float* dst;
            const float* xr = nullptr;
            if (MODE == 0) {
                const int part = o >> 8, co = o & 255;
                float* basep = (part == 0) ? g_q : (part == 1) ? g_k : g_v;
                dst = basep + ((size_t)(b*CC_ + co))*HWN + n0;
            } else {
                const size_t off = ((size_t)(b*CC_ + o))*HWN + n0;
                dst = out + off;
                xr  = xres + off;
            }
            #pragma unroll
            for (int j = 0; j < 4; j++) {
                const int col = wn*32 + j*8 + (lane & 3)*2;
                float2 t;
                t.x = acc[i][j][half*2+0] + bv;
                t.y = acc[i][j][half*2+1] + bv;
                if (MODE == 1) { t.x += xr[col]; t.y += xr[col+1]; }
                *(float2*)(dst + col) = t;
            }
        }
    }
}

// ---------------------------------------------------------------- 4) mix
__global__ __launch_bounds__(256) void mix_kernel()
{
    const int be = blockIdx.x;
    const int b  = be >> 6;
    const int e  = be & 63;
    const int tid = threadIdx.x;

    const size_t base = (size_t)(b*CC_ + e) * HWN;
    const float* qp = g_q + base;
    const float* kp = g_k + base;
    const float* vp = g_v + base;

    float acc[16] = {};
    for (int s = tid; s < HWN; s += 256) {
        float qv[4], kv[4];
        #pragma unroll
        for (int i = 0; i < 4; i++) qv[i] = qp[(size_t)i*64*HWN + s];
        #pragma unroll
        for (int j = 0; j < 4; j++) kv[j] = kp[(size_t)j*64*HWN + s];
        #pragma unroll
        for (int i = 0; i < 4; i++)
            #pragma unroll
            for (int j = 0; j < 4; j++)
                acc[i*4+j] += qv[i] * kv[j];
    }

    __shared__ float red[16][264];
    __shared__ float P[4][4];
    #pragma unroll
    for (int v = 0; v < 16; v++) red[v][tid] = acc[v];
    __syncthreads();

    if (tid < 16) {
        float s = 0.f;
        for (int t = 0; t < 256; t++) s += red[tid][t];
        red[tid][256] = s * 0.125f;
    }
    __syncthreads();
    if (tid < 4) {
        float g0 = red[tid*4+0][256], g1 = red[tid*4+1][256];
        float g2 = red[tid*4+2][256], g3 = red[tid*4+3][256];
        float m = fmaxf(fmaxf(g0, g1), fmaxf(g2, g3));
        float e0 = expf(g0-m), e1 = expf(g1-m), e2 = expf(g2-m), e3 = expf(g3-m);
        float inv = 1.f / (e0+e1+e2+e3);
        P[tid][0] = e0*inv; P[tid][1] = e1*inv; P[tid][2] = e2*inv; P[tid][3] = e3*inv;
    }
    __syncthreads();

    float p[4][4];
    #pragma unroll
    for (int i = 0; i < 4; i++)
        #pragma unroll
        for (int j = 0; j < 4; j++) p[i][j] = P[i][j];

    for (int s = tid; s < HWN; s += 256) {
        float vv[4];
        #pragma unroll
        for (int j = 0; j < 4; j++) vv[j] = vp[(size_t)j*64*HWN + s];
        #pragma unroll
        for (int i = 0; i < 4; i++) {
            float o = p[i][0]*vv[0] + p[i][1]*vv[1] + p[i][2]*vv[2] + p[i][3]*vv[3];
            g_ao[base + (size_t)i*64*HWN + s] = o;
        }
    }
}

// ------------------------------------------- 5) transpose ao -> bf16 hi/lo [b][n][c]
__global__ __launch_bounds__(256) void trans_ao_kernel()
{
    const int nt = blockIdx.x, ct = blockIdx.y, b = blockIdx.z;
    const int n0 = nt*32, c0 = ct*32;
    __shared__ float tile[32][33];
    const int col = threadIdx.x & 31, r = threadIdx.x >> 5;
    #pragma unroll
    for (int p = 0; p < 4; p++) {
        int cl = r + p*8;
        tile[cl][col] = g_ao[((size_t)(b*CC_ + c0 + cl))*HWN + n0 + col];
    }
    __syncthreads();
    #pragma unroll
    for (int p = 0; p < 4; p++) {
        int nl = r + p*8;
        float v = tile[col][nl];
        __nv_bfloat16 hi = __float2bfloat16(v);
        __nv_bfloat16 lo = __float2bfloat16(v - __bfloat162float(hi));
        size_t idx = ((size_t)(b*HWN + n0 + nl))*CC_ + c0 + col;
        g_aoT_hi[idx] = hi; g_aoT_lo[idx] = lo;
    }
}

// ---------------------------------------------------------------- launch
extern "C" void kernel_launch(void* const* d_in, const int* in_sizes, int n_in,
                              void* d_out, int out_size)
{
    const float* x      = (const float*)d_in[0];
    const float* norm_w = (const float*)d_in[1];
    const float* norm_b = (const float*)d_in[2];
    const float* qkv_w  = (const float*)d_in[3];
    const float* qkv_b  = (const float*)d_in[4];
    const float* proj_w = (const float*)d_in[5];
    const float* proj_b = (const float*)d_in[6];
    float* out = (float*)d_out;

    static bool attr_set = false;
    if (!attr_set) {
        cudaFuncSetAttribute(hmma_gemm_kernel<0>,
                             cudaFuncAttributeMaxDynamicSharedMemorySize, SMEM_TOTAL_MMA);
        cudaFuncSetAttribute(hmma_gemm_kernel<1>,
                             cudaFuncAttributeMaxDynamicSharedMemorySize, SMEM_TOTAL_MMA);
        attr_set = true;
    }

    gn_stats_kernel<<<BB*8, 256>>>(x);
    wprep_kernel<<<768, 256>>>(qkv_w, proj_w);
    gn_apply_t_kernel<<<dim3(128, 8, BB), 256>>>(x, norm_w, norm_b);
    hmma_gemm_kernel<0><<<dim3(32, 6, BB), 256, SMEM_TOTAL_MMA>>>(qkv_b, nullptr, nullptr);
    mix_kernel<<<BB*64, 256>>>();
    trans_ao_kernel<<<dim3(128, 8, BB), 256>>>();
    hmma_gemm_kernel<1><<<dim3(32, 2, BB), 256, SMEM_TOTAL_MMA>>>(proj_b, x, out);
}

// round 10
// speedup vs baseline: 4.7481x; 1.0995x over previous
#include <cuda_runtime.h>
#include <cuda_bf16.h>
#include <cstdint>

// ---------------------------------------------------------------- constants
#define BB 16
#define CC_ 256
#define HWN 4096
#define EPSV 1e-5f
#define TOTAL (BB*CC_*HWN)   // 16,777,216

// ---------------------------------------------------------------- scratch
__device__ float g_q [TOTAL];
__device__ float g_k [TOTAL];
__device__ float g_v [TOTAL];
__device__ float g_ao[TOTAL];
__device__ __nv_bfloat16 g_xnT_hi[TOTAL];
__device__ __nv_bfloat16 g_xnT_lo[TOTAL];
__device__ __nv_bfloat16 g_aoT_hi[TOTAL];
__device__ __nv_bfloat16 g_aoT_lo[TOTAL];
__device__ __nv_bfloat16 g_wqkv_hi[768*256];
__device__ __nv_bfloat16 g_wqkv_lo[768*256];
__device__ __nv_bfloat16 g_wproj_hi[256*256];
__device__ __nv_bfloat16 g_wproj_lo[256*256];
__device__ float g_mean[BB*8];
__device__ float g_rstd[BB*8];

// ---------------------------------------------------------------- PTX helpers
__device__ __forceinline__ uint32_t smem_u32(const void* p) {
    uint32_t a;
    asm("{ .reg .u64 t; cvta.to.shared.u64 t, %1; cvt.u32.u64 %0, t; }" : "=r"(a) : "l"(p));
    return a;
}
__device__ __forceinline__ void ldsm4(uint32_t* r, uint32_t addr) {
    asm volatile("ldmatrix.sync.aligned.m8n8.x4.shared.b16 {%0,%1,%2,%3}, [%4];"
                 : "=r"(r[0]), "=r"(r[1]), "=r"(r[2]), "=r"(r[3]) : "r"(addr));
}
__device__ __forceinline__ void mma16816(float* d, const uint32_t* a, const uint32_t* b) {
    asm volatile("mma.sync.aligned.m16n8k16.row.col.f32.bf16.bf16.f32 "
                 "{%0,%1,%2,%3}, {%4,%5,%6,%7}, {%8,%9}, {%0,%1,%2,%3};"
                 : "+f"(d[0]), "+f"(d[1]), "+f"(d[2]), "+f"(d[3])
                 : "r"(a[0]), "r"(a[1]), "r"(a[2]), "r"(a[3]), "r"(b[0]), "r"(b[1]));
}
__device__ __forceinline__ void cpasync16(uint32_t dst, const void* src) {
    asm volatile("cp.async.cg.shared.global [%0], [%1], 16;" :: "r"(dst), "l"(src));
}
#define CP_COMMIT() asm volatile("cp.async.commit_group;" ::: "memory")
#define CP_WAIT(n)  asm volatile("cp.async.wait_group %0;" :: "n"(n) : "memory")

// 16B-unit swizzled offset inside an 8KB region: 128 rows x 4 units (64B row)
__device__ __forceinline__ uint32_t swz_unit(int row, int u) {
    return (uint32_t)((row*4 + (u ^ ((row >> 1) & 3))) * 16);
}

// ---------------------------------------------------------------- 1) GN stats
__global__ __launch_bounds__(256) void gn_stats_kernel(const float* __restrict__ x)
{
    const int bg  = blockIdx.x;
    const int tid = threadIdx.x;
    const float4* p4 = (const float4*)(x + (size_t)bg * 32 * HWN);
    float s = 0.f, s2 = 0.f;
    for (int i = tid; i < 32*HWN/4; i += 256) {
        float4 v = p4[i];
        s  += v.x + v.y + v.z + v.w;
        s2 += v.x*v.x + v.y*v.y + v.z*v.z + v.w*v.w;
    }
    __shared__ float rs[256], rs2[256];
    rs[tid] = s; rs2[tid] = s2;
    __syncthreads();
    for (int off = 128; off > 0; off >>= 1) {
        if (tid < off) { rs[tid] += rs[tid+off]; rs2[tid] += rs2[tid+off]; }
        __syncthreads();
    }
    if (tid == 0) {
        const float inv_n = 1.f / (float)(32*HWN);
        float mean = rs[0] * inv_n;
        float var  = rs2[0] * inv_n - mean*mean;
        g_mean[bg] = mean;
        g_rstd[bg] = rsqrtf(var + EPSV);
    }
}

// ------------------------------------------- 2) GN apply + transpose -> bf16 hi/lo [b][n][c]
__global__ __launch_bounds__(256) void gn_apply_t_kernel(const float* __restrict__ x,
                                                         const float* __restrict__ nw,
                                                         const float* __restrict__ nb)
{
    const int nt = blockIdx.x, ct = blockIdx.y, b = blockIdx.z;
    const int n0 = nt*32, c0 = ct*32;
    __shared__ float tile[32][33];
    const int col = threadIdx.x & 31, r = threadIdx.x >> 5;
    #pragma unroll
    for (int p = 0; p < 4; p++) {
        int cl = r + p*8;
        int c = c0 + cl;
        float rstd = g_rstd[b*8 + (c >> 5)];
        float mean = g_mean[b*8 + (c >> 5)];
        float sw = nw[c]*rstd, sb2 = nb[c] - mean*sw;
        float v = x[((size_t)(b*CC_+c))*HWN + n0 + col];
        tile[cl][col] = v*sw + sb2;
    }
    __syncthreads();
    #pragma unroll
    for (int p = 0; p < 4; p++) {
        int nl = r + p*8;
        float v = tile[col][nl];
        __nv_bfloat16 hi = __float2bfloat16(v);
        __nv_bfloat16 lo = __float2bfloat16(v - __bfloat162float(hi));
        size_t idx = ((size_t)(b*HWN + n0 + nl))*CC_ + c0 + col;
        g_xnT_hi[idx] = hi; g_xnT_lo[idx] = lo;
    }
}

// ---------------------------------------------------------------- 3) weight prep
__global__ __launch_bounds__(256) void wprep_kernel(const float* __restrict__ qkv_w,
                                                    const float* __restrict__ proj_w)
{
    const int i = blockIdx.x * 256 + threadIdx.x;
    if (i < 768*256) {
        float v = qkv_w[i];
        __nv_bfloat16 hi = __float2bfloat16(v);
        g_wqkv_hi[i] = hi;
        g_wqkv_lo[i] = __float2bfloat16(v - __bfloat162float(hi));
    }
    if (i < 256*256) {
        float v = proj_w[i];
        __nv_bfloat16 hi = __float2bfloat16(v);
        g_wproj_hi[i] = hi;
        g_wproj_lo[i] = __float2bfloat16(v - __bfloat162float(hi));
    }
}

// ---------------------------------------------------------------- HMMA GEMM
// D[m0+row, n0+col] = sum_c W[m0+row, c] * X[b, n0+col, c]   (K=256, 8 chunks of 32)
// CTA tile 128x128, 8 warps (2 along M x 4 along N), warp tile 64x32.
// 3 passes: Ahi*Bhi + Alo*Bhi + Ahi*Blo (ordered for register liveness).
// 3-stage cp.async pipeline, 2 CTAs/SM (96KB smem, <=128 regs).
// MODE 0: qkv -> q/k/v fp32 [b][c][n] (+bias). MODE 1: proj -> out = D + bias + x.
#define STAGE_BYTES 32768
#define NSTAGE 3
#define SMEM_TOTAL_MMA (STAGE_BYTES*NSTAGE)   // 98304

template<int MODE>
__global__ __launch_bounds__(256, 2) void hmma_gemm_kernel(const float* __restrict__ bias,
                                                           const float* __restrict__ xres,
                                                           float* __restrict__ out)
{
    extern __shared__ char smem[];
    const uint32_t sb = smem_u32(smem);
    const int tid = threadIdx.x;
    const int lane = tid & 31, wid = tid >> 5;
    const int wm = wid & 1, wn = wid >> 1;
    const int n0 = blockIdx.x * 128, m0 = blockIdx.y * 128, b = blockIdx.z;

    const __nv_bfloat16* __restrict__ Whi = (MODE == 0) ? g_wqkv_hi : g_wproj_hi;
    const __nv_bfloat16* __restrict__ Wlo = (MODE == 0) ? g_wqkv_lo : g_wproj_lo;
    const __nv_bfloat16* __restrict__ Xhi = (MODE == 0) ? g_xnT_hi  : g_aoT_hi;
    const __nv_bfloat16* __restrict__ Xlo = (MODE == 0) ? g_xnT_lo  : g_aoT_lo;

    float acc[4][4][4] = {};

    const int row_a = tid >> 2, u_a = tid & 3;

    auto load_chunk = [&](int chunk, int stage) {
        const int c0 = chunk * 32;
        const uint32_t base = sb + (uint32_t)stage * STAGE_BYTES;
        #pragma unroll
        for (int it = 0; it < 2; it++) {
            const int row = row_a + it*64;
            const uint32_t du = swz_unit(row, u_a);
            const size_t sa = (size_t)(m0 + row)*256 + c0 + u_a*8;
            cpasync16(base +         du, Whi + sa);
            cpasync16(base + 8192u + du, Wlo + sa);
            const size_t sx = (size_t)(b*HWN + n0 + row)*256 + c0 + u_a*8;
            cpasync16(base + 16384u + du, Xhi + sx);
            cpasync16(base + 24576u + du, Xlo + sx);
        }
        CP_COMMIT();
    };

    auto compute = [&](int stage) {
        const uint32_t base = sb + (uint32_t)stage * STAGE_BYTES;
        #pragma unroll
        for (int ks = 0; ks < 2; ks++) {
            uint32_t a0[4][4], a1[4][4], bb0[4][2], bb1[4][2];
            // A-hi + B-hi
            #pragma unroll
            for (int i = 0; i < 4; i++) {
                const int row = wm*64 + i*16 + (lane & 15);
                const int u   = ks*2 + (lane >> 4);
                ldsm4(a0[i], base + swz_unit(row, u));
            }
            #pragma unroll
            for (int jj = 0; jj < 2; jj++) {
                const int row = wn*32 + jj*16 + ((lane >> 4) & 1)*8 + (lane & 7);
                const int u   = ks*2 + ((lane >> 3) & 1);
                uint32_t r[4];
                ldsm4(r, base + 16384u + swz_unit(row, u));
                bb0[jj*2+0][0] = r[0]; bb0[jj*2+0][1] = r[1];
                bb0[jj*2+1][0] = r[2]; bb0[jj*2+1][1] = r[3];
            }
            #pragma unroll
            for (int i = 0; i < 4; i++)
                #pragma unroll
                for (int j = 0; j < 4; j++)
                    mma16816(acc[i][j], a0[i], bb0[j]);   // Ahi*Bhi
            // A-lo
            #pragma unroll
            for (int i = 0; i < 4; i++) {
                const int row = wm*64 + i*16 + (lane & 15);
                const int u   = ks*2 + (lane >> 4);
                ldsm4(a1[i], base + 8192u + swz_unit(row, u));
            }
            #pragma unroll
            for (int i = 0; i < 4; i++)
                #pragma unroll
                for (int j = 0; j < 4; j++)
                    mma16816(acc[i][j], a1[i], bb0[j]);   // Alo*Bhi
            // B-lo (a1 dead from here; bb1 can reuse its registers)
            #pragma unroll
            for (int jj = 0; jj < 2; jj++) {
                const int row = wn*32 + jj*16 + ((lane >> 4) & 1)*8 + (lane & 7);
                const int u   = ks*2 + ((lane >> 3) & 1);
                uint32_t r[4];
                ldsm4(r, base + 24576u + swz_unit(row, u));
                bb1[jj*2+0][0] = r[0]; bb1[jj*2+0][1] = r[1];
                bb1[jj*2+1][0] = r[2]; bb1[jj*2+1][1] = r[3];
            }
            #pragma unroll
            for (int i = 0; i < 4; i++)
                #pragma unroll
                for (int j = 0; j < 4; j++)
                    mma16816(acc[i][j], a0[i], bb1[j]);   // Ahi*Blo
        }
    };

    // prefetch 2 chunks
    load_chunk(0, 0);
    load_chunk(1, 1);

    #pragma unroll
    for (int c = 0; c < 8; c++) {
        if (c < 7) CP_WAIT(1);
        else CP_WAIT(0);
        __syncthreads();
        // stage (c+2)%3 was consumed at iter c-1 -> safe to refill after this barrier
        if (c + 2 < 8) load_chunk(c + 2, (c + 2) % 3);
        compute(c % 3);
    }

    // ---------------- epilogue ----------------
    #pragma unroll
    for (int i = 0; i < 4; i++) {
        const int row0 = m0 + wm*64 + i*16 + (lane >> 2);
        #pragma unroll
        for (int half = 0; half < 2; half++) {
            const int o = row0 + half*8;
            const float bv = bias[o];
            float* dst;
            const float* xr = nullptr;
            if (MODE == 0) {
                const int part = o >> 8, co = o & 255;
                float* basep = (part == 0) ? g_q : (part == 1) ? g_k : g_v;
                dst = basep + ((size_t)(b*CC_ + co))*HWN + n0;
            } else {
                const size_t off = ((size_t)(b*CC_ + o))*HWN + n0;
                dst = out + off;
                xr  = xres + off;
            }
            #pragma unroll
            for (int j = 0; j < 4; j++) {
                const int col = wn*32 + j*8 + (lane & 3)*2;
                float2 t;
                t.x = acc[i][j][half*2+0] + bv;
                t.y = acc[i][j][half*2+1] + bv;
                if (MODE == 1) { t.x += xr[col]; t.y += xr[col+1]; }
                *(float2*)(dst + col) = t;
            }
        }
    }
}

// ---------------------------------------------------------------- 4) mix
__global__ __launch_bounds__(256) void mix_kernel()
{
    const int be = blockIdx.x;
    const int b  = be >> 6;
    const int e  = be & 63;
    const int tid = threadIdx.x;

    const size_t base = (size_t)(b*CC_ + e) * HWN;
    const float* qp = g_q + base;
    const float* kp = g_k + base;
    const float* vp = g_v + base;

    float acc[16] = {};
    for (int s = tid; s < HWN; s += 256) {
        float qv[4], kv[4];
        #pragma unroll
        for (int i = 0; i < 4; i++) qv[i] = qp[(size_t)i*64*HWN + s];
        #pragma unroll
        for (int j = 0; j < 4; j++) kv[j] = kp[(size_t)j*64*HWN + s];
        #pragma unroll
        for (int i = 0; i < 4; i++)
            #pragma unroll
            for (int j = 0; j < 4; j++)
                acc[i*4+j] += qv[i] * kv[j];
    }

    __shared__ float red[16][264];
    __shared__ float P[4][4];
    #pragma unroll
    for (int v = 0; v < 16; v++) red[v][tid] = acc[v];
    __syncthreads();

    if (tid < 16) {
        float s = 0.f;
        for (int t = 0; t < 256; t++) s += red[tid][t];
        red[tid][256] = s * 0.125f;
    }
    __syncthreads();
    if (tid < 4) {
        float g0 = red[tid*4+0][256], g1 = red[tid*4+1][256];
        float g2 = red[tid*4+2][256], g3 = red[tid*4+3][256];
        float m = fmaxf(fmaxf(g0, g1), fmaxf(g2, g3));
        float e0 = expf(g0-m), e1 = expf(g1-m), e2 = expf(g2-m), e3 = expf(g3-m);
        float inv = 1.f / (e0+e1+e2+e3);
        P[tid][0] = e0*inv; P[tid][1] = e1*inv; P[tid][2] = e2*inv; P[tid][3] = e3*inv;
    }
    __syncthreads();

    float p[4][4];
    #pragma unroll
    for (int i = 0; i < 4; i++)
        #pragma unroll
        for (int j = 0; j < 4; j++) p[i][j] = P[i][j];

    for (int s = tid; s < HWN; s += 256) {
        float vv[4];
        #pragma unroll
        for (int j = 0; j < 4; j++) vv[j] = vp[(size_t)j*64*HWN + s];
        #pragma unroll
        for (int i = 0; i < 4; i++) {
            float o = p[i][0]*vv[0] + p[i][1]*vv[1] + p[i][2]*vv[2] + p[i][3]*vv[3];
            g_ao[base + (size_t)i*64*HWN + s] = o;
        }
    }
}

// ------------------------------------------- 5) transpose ao -> bf16 hi/lo [b][n][c]
__global__ __launch_bounds__(256) void trans_ao_kernel()
{
    const int nt = blockIdx.x, ct = blockIdx.y, b = blockIdx.z;
    const int n0 = nt*32, c0 = ct*32;
    __shared__ float tile[32][33];
    const int col = threadIdx.x & 31, r = threadIdx.x >> 5;
    #pragma unroll
    for (int p = 0; p < 4; p++) {
        int cl = r + p*8;
        tile[cl][col] = g_ao[((size_t)(b*CC_ + c0 + cl))*HWN + n0 + col];
    }
    __syncthreads();
    #pragma unroll
    for (int p = 0; p < 4; p++) {
        int nl = r + p*8;
        float v = tile[col][nl];
        __nv_bfloat16 hi = __float2bfloat16(v);
        __nv_bfloat16 lo = __float2bfloat16(v - __bfloat162float(hi));
        size_t idx = ((size_t)(b*HWN + n0 + nl))*CC_ + c0 + col;
        g_aoT_hi[idx] = hi; g_aoT_lo[idx] = lo;
    }
}

// ---------------------------------------------------------------- launch
extern "C" void kernel_launch(void* const* d_in, const int* in_sizes, int n_in,
                              void* d_out, int out_size)
{
    const float* x      = (const float*)d_in[0];
    const float* norm_w = (const float*)d_in[1];
    const float* norm_b = (const float*)d_in[2];
    const float* qkv_w  = (const float*)d_in[3];
    const float* qkv_b  = (const float*)d_in[4];
    const float* proj_w = (const float*)d_in[5];
    const float* proj_b = (const float*)d_in[6];
    float* out = (float*)d_out;

    static bool attr_set = false;
    if (!attr_set) {
        cudaFuncSetAttribute(hmma_gemm_kernel<0>,
                             cudaFuncAttributeMaxDynamicSharedMemorySize, SMEM_TOTAL_MMA);
        cudaFuncSetAttribute(hmma_gemm_kernel<1>,
                             cudaFuncAttributeMaxDynamicSharedMemorySize, SMEM_TOTAL_MMA);
        attr_set = true;
    }

    gn_stats_kernel<<<BB*8, 256>>>(x);
    wprep_kernel<<<768, 256>>>(qkv_w, proj_w);
    gn_apply_t_kernel<<<dim3(128, 8, BB), 256>>>(x, norm_w, norm_b);
    hmma_gemm_kernel<0><<<dim3(32, 6, BB), 256, SMEM_TOTAL_MMA>>>(qkv_b, nullptr, nullptr);
    mix_kernel<<<BB*64, 256>>>();
    trans_ao_kernel<<<dim3(128, 8, BB), 256>>>();
    hmma_gemm_kernel<1><<<dim3(32, 2, BB), 256, SMEM_TOTAL_MMA>>>(proj_b, x, out);
}